// round 13
// baseline (speedup 1.0000x reference)
#include <cuda_runtime.h>

#define NN 512
#define DD 32
#define TT 8192
#define TPB 256            // 2 neurons per thread
#define TWO_PI 6.2831853071795864769f
#define INV_TWO_PI 0.15915494309189535f

// precomputed S[t] = sum_d x_t[d] * x_{t+1}[d]  (complex)
__device__ __align__(8) float2 Sbuf[TT];

// ---- packed f32x2 helpers (sm_100+) ----
__device__ __forceinline__ unsigned long long ffma2(unsigned long long a,
                                                    unsigned long long b,
                                                    unsigned long long c) {
    unsigned long long d;
    asm("fma.rn.f32x2 %0, %1, %2, %3;" : "=l"(d) : "l"(a), "l"(b), "l"(c));
    return d;
}
__device__ __forceinline__ unsigned long long pack2(float lo, float hi) {
    unsigned long long r;
    asm("mov.b64 %0, {%1, %2};" : "=l"(r) : "f"(lo), "f"(hi));
    return r;
}
__device__ __forceinline__ void unpack2(unsigned long long v, float& lo, float& hi) {
    asm("mov.b64 {%0, %1}, %2;" : "=f"(lo), "=f"(hi) : "l"(v));
}
__device__ __forceinline__ float wrap2pi(float x) {
    return x - floorf(x * INV_TWO_PI) * TWO_PI;
}
__device__ __forceinline__ float frcp(float x) {
    float r;
    asm("rcp.approx.f32 %0, %1;" : "=f"(r) : "f"(x));
    return r;
}

// ---- parallel pre-kernel: S[t] for all t ----
__global__ void precomp_s(const float* __restrict__ Xr, const float* __restrict__ Xi) {
    int t = blockIdx.x * 256 + threadIdx.x;
    if (t >= TT) return;
    float sr = 0.f, si = 0.f;
    if (t + 1 < TT) {
        const float4* cr = (const float4*)(Xr + t * DD);
        const float4* ci = (const float4*)(Xi + t * DD);
        const float4* nr = (const float4*)(Xr + (t + 1) * DD);
        const float4* ni = (const float4*)(Xi + (t + 1) * DD);
#pragma unroll
        for (int j = 0; j < DD / 4; j++) {
            float4 a = cr[j], b = ci[j], c = nr[j], d = ni[j];
            sr += a.x * c.x - b.x * d.x;  si += a.x * d.x + b.x * c.x;
            sr += a.y * c.y - b.y * d.y;  si += a.y * d.y + b.y * c.y;
            sr += a.z * c.z - b.z * d.z;  si += a.z * d.z + b.z * c.z;
            sr += a.w * c.w - b.w * d.w;  si += a.w * d.w + b.w * c.w;
        }
    }
    Sbuf[t] = make_float2(sr, si);
}

__global__ __launch_bounds__(TPB, 1)
void rds_kernel(const float* __restrict__ Xr, const float* __restrict__ Xi,
                const float* __restrict__ tw, const float* __restrict__ Wr,
                const float* __restrict__ Wi, const float* __restrict__ phi0,
                const float* __restrict__ beta0, float* __restrict__ out) {
    const int tid  = threadIdx.x;
    const int lane = tid & 31;
    const int wid  = tid >> 5;              // 0..7

    // 4-way buffered per-step shared state
    __shared__ __align__(16) float4 xsA[4][DD];     // (xr,xr,xi,xi) per d
    __shared__ __align__(16) float  xsB[4][2 * DD]; // interleaved (xr,xi)
    __shared__ float  s_tgt[4];
    __shared__ __align__(16) float red[2][8];       // per-warp partials

    // factored W: W = alpha * A ; A packed (ar,ai) per d, per neuron
    unsigned long long A[2][DD];            // 128 regs
    float alpha[2] = {1.0f, 1.0f};
    float phi[2], beta[2], lt[2], gamma[2], dtl[2], sn[2], cs[2];
    float zr[2], zi[2];
    float err = 0.0f;                       // identical in every thread

#pragma unroll
    for (int n = 0; n < 2; n++) {
        const int g = tid + n * TPB;
#pragma unroll
        for (int d = 0; d < DD; d++)
            A[n][d] = pack2(Wr[g * DD + d], Wi[g * DD + d]);
        phi[n]  = phi0[g];
        beta[n] = beta0[g];
        lt[n]   = 0.0f;
    }

    float* outs   = out;
    float* betas  = out + TT;
    float* gammas = out + TT + (size_t)TT * NN;

    // prologue: x_0 -> buf0, x_1 -> buf1
    if (tid < DD) {
        float xr = Xr[tid], xi = Xi[tid];
        xsA[0][tid] = make_float4(xr, xr, xi, xi);
        xsB[0][2 * tid] = xr; xsB[0][2 * tid + 1] = xi;
        xr = Xr[DD + tid]; xi = Xi[DD + tid];
        xsA[1][tid] = make_float4(xr, xr, xi, xi);
        xsB[1][2 * tid] = xr; xsB[1][2 * tid + 1] = xi;
        if (tid == 0) { s_tgt[0] = tw[0]; s_tgt[1] = tw[1]; }
    }

    // pipelined head for step 0 (theta recomputed from lt each step — R10 form)
#pragma unroll
    for (int n = 0; n < 2; n++) {
        gamma[n] = __expf(-0.5f * beta[n]);
        dtl[n]   = gamma[n] * 1e-3f;
        lt[n]   += dtl[n];
        __sincosf(wrap2pi(10.0f * lt[n] + phi[n]), &sn[n], &cs[n]);
    }

    __syncthreads();

    // Z_0 = A @ x_0 (alpha = 1), both neurons fused over shared x loads
    {
        unsigned long long aA0 = 0ull, aB0 = 0ull, aA1 = 0ull, aB1 = 0ull;
        const ulonglong2* xa = (const ulonglong2*)xsA[0];
#pragma unroll 8
        for (int d = 0; d < DD; d++) {
            ulonglong2 v = xa[d];
            aA0 = ffma2(A[0][d], v.x, aA0);
            aB0 = ffma2(A[0][d], v.y, aB0);
            aA1 = ffma2(A[1][d], v.x, aA1);
            aB1 = ffma2(A[1][d], v.y, aB1);
        }
        float a0l, a0h, b0l, b0h, a1l, a1h, b1l, b1h;
        unpack2(aA0, a0l, a0h); unpack2(aB0, b0l, b0h);
        unpack2(aA1, a1l, a1h); unpack2(aB1, b1l, b1h);
        zr[0] = a0l - b0h;  zi[0] = b0l + a0h;
        zr[1] = a1l - b1h;  zi[1] = b1l + a1h;
    }

#pragma unroll 1
    for (int t = 0; t < TT; t++) {
        const int b  = t & 3;
        const int bn = (t + 1) & 3;
        const int bp = (t + 2) & 3;
        const int rb = t & 1;

        // ================= PRE-BARRIER =================
        float Y[2], v = 0.0f;
#pragma unroll
        for (int n = 0; n < 2; n++) {
            float dot = cs[n] * zr[n] + sn[n] * zi[n];
            Y[n] = fmaxf(dot, 0.0f);
            v += Y[n] * cs[n];
        }
#pragma unroll
        for (int o = 16; o; o >>= 1)
            v += __shfl_xor_sync(0xffffffffu, v, o);
        if (lane == 0) red[rb][wid] = v;

        // prefetch x_{t+2}, tgt_{t+2}
        if (tid < DD && t + 2 < TT) {
            float xr = Xr[(t + 2) * DD + tid];
            float xi = Xi[(t + 2) * DD + tid];
            xsA[bp][tid] = make_float4(xr, xr, xi, xi);
            xsB[bp][2 * tid]     = xr;
            xsB[bp][2 * tid + 1] = xi;
            if (tid == 0) s_tgt[bp] = tw[t + 2];
        }

        // U = A @ x_{t+1}, both neurons fused (shared x loads)
        float ur[2], ui[2];
        {
            unsigned long long aA0 = 0ull, aB0 = 0ull, aA1 = 0ull, aB1 = 0ull;
            const ulonglong2* xa = (const ulonglong2*)xsA[bn];
#pragma unroll 8
            for (int d = 0; d < DD; d++) {
                ulonglong2 vv = xa[d];
                aA0 = ffma2(A[0][d], vv.x, aA0);
                aB0 = ffma2(A[0][d], vv.y, aB0);
                aA1 = ffma2(A[1][d], vv.x, aA1);
                aB1 = ffma2(A[1][d], vv.y, aB1);
            }
            float a0l, a0h, b0l, b0h, a1l, a1h, b1l, b1h;
            unpack2(aA0, a0l, a0h); unpack2(aB0, b0l, b0h);
            unpack2(aA1, a1l, a1h); unpack2(aB1, b1l, b1h);
            ur[0] = a0l - b0h;  ui[0] = b0l + a0h;
            ur[1] = a1l - b1h;  ui[1] = b1l + a1h;
        }

        float2 S  = __ldg(&Sbuf[t]);
        float tgt = s_tgt[b];

        // chain hoists (depend only on pre-barrier values)
        float rcp_at = frcp(fabsf(tgt) + 0.01f);
        float dphi[2], ex1[2];
#pragma unroll
        for (int n = 0; n < 2; n++) {
            dphi[n] = (2.0f / 512.0f) * (-tgt * sn[n]) * dtl[n];
            ex1[n]  = 1.0f - __expf(-2e-3f * (gamma[n] + 1e-6f));
        }

        __syncthreads();   // the single per-step barrier

        // ================= POST-BARRIER =================
        float4 r0 = *(const float4*)&red[rb][0];
        float4 r1 = *(const float4*)&red[rb][4];
        float out_v = ((r0.x + r0.y) + (r0.z + r0.w))
                    + ((r1.x + r1.y) + (r1.z + r1.w));

        // shared scalar feedback (identical in all threads)
        err = 0.99f * err + 0.01f * fabsf(tgt - out_v);
        float btgt = 3.5f * __expf(-5.0f * (err * rcp_at));

        unsigned long long cpk[2];
#pragma unroll
        for (int n = 0; n < 2; n++) {
            float a_s  = (btgt > beta[n]) ? ex1[n] : 0.03278394f; // 1-exp(-1/30)
            float bnew = beta[n] + a_s * (btgt - beta[n]);
            bnew = fminf(fmaxf(bnew, 0.005f), 5.0f);

            float gg  = 0.05f * Y[n] * dtl[n];
            float ddc = bnew * Y[n] * Y[n] * dtl[n];
            float one = 1.0f - ddc;

            // Z_{t+1} = one * (alpha * U) + gg * S
            float au = one * alpha[n];
            zr[n] = au * ur[n] + gg * S.x;
            zi[n] = au * ui[n] + gg * S.y;

            // factored W update: alpha' = alpha*one ; A += (gg/alpha')*x_t
            float an = alpha[n] * one;
            float c  = __fdividef(gg, an);
            alpha[n] = an;
            cpk[n]   = pack2(c, c);

            // outputs
            const int g = tid + n * TPB;
            betas[t * NN + g]  = bnew;
            gammas[t * NN + g] = gamma[n];

            // phase pull + wrap (R10 form: phi wrapped, theta from lt)
            float phin = phi[n] + dphi[n];
            phin -= floorf(phin * INV_TWO_PI) * TWO_PI;
            phi[n] = phin;

            // pipelined head of next step
            beta[n]  = bnew;
            gamma[n] = __expf(-0.5f * bnew);
            dtl[n]   = gamma[n] * 1e-3f;
            lt[n]   += dtl[n];
            __sincosf(wrap2pi(10.0f * lt[n] + phin), &sn[n], &cs[n]);
        }
        if (tid == 0) outs[t] = out_v;

        // A update, both neurons fused (shared x_t loads)
        {
            const ulonglong2* xb = (const ulonglong2*)xsB[b];
#pragma unroll 8
            for (int j = 0; j < DD / 2; j++) {
                ulonglong2 u = xb[j];
                A[0][2 * j]     = ffma2(cpk[0], u.x, A[0][2 * j]);
                A[0][2 * j + 1] = ffma2(cpk[0], u.y, A[0][2 * j + 1]);
                A[1][2 * j]     = ffma2(cpk[1], u.x, A[1][2 * j]);
                A[1][2 * j + 1] = ffma2(cpk[1], u.y, A[1][2 * j + 1]);
            }
        }

        // periodic renormalization: fold alpha into A
        if ((t & 127) == 127) {
#pragma unroll
            for (int n = 0; n < 2; n++) {
                unsigned long long apk = pack2(alpha[n], alpha[n]);
#pragma unroll 8
                for (int d = 0; d < DD; d++)
                    A[n][d] = ffma2(apk, A[n][d], 0ull);
                alpha[n] = 1.0f;
            }
        }
    }
}

extern "C" void kernel_launch(void* const* d_in, const int* in_sizes, int n_in,
                              void* d_out, int out_size) {
    const float* Xr    = (const float*)d_in[0];
    const float* Xi    = (const float*)d_in[1];
    const float* tw    = (const float*)d_in[2];
    const float* Wr    = (const float*)d_in[3];
    const float* Wi    = (const float*)d_in[4];
    const float* phi0  = (const float*)d_in[5];
    const float* beta0 = (const float*)d_in[6];
    float* out = (float*)d_out;
    precomp_s<<<TT / 256, 256>>>(Xr, Xi);
    rds_kernel<<<1, TPB>>>(Xr, Xi, tw, Wr, Wi, phi0, beta0, out);
}

// round 14
// speedup vs baseline: 3.5161x; 3.5161x over previous
#include <cuda_runtime.h>

#define NN 512
#define DD 32
#define TT 8192
#define TPB 256            // 2 neurons per thread
#define TWO_PI 6.2831853071795864769f
#define INV_TWO_PI 0.15915494309189535f

// precomputed S[t] = sum_d x_t[d] * x_{t+1}[d]  (complex)
__device__ __align__(8) float2 Sbuf[TT];

// ---- packed f32x2 helpers (sm_100+) ----
__device__ __forceinline__ unsigned long long ffma2(unsigned long long a,
                                                    unsigned long long b,
                                                    unsigned long long c) {
    unsigned long long d;
    asm("fma.rn.f32x2 %0, %1, %2, %3;" : "=l"(d) : "l"(a), "l"(b), "l"(c));
    return d;
}
__device__ __forceinline__ unsigned long long pack2(float lo, float hi) {
    unsigned long long r;
    asm("mov.b64 %0, {%1, %2};" : "=l"(r) : "f"(lo), "f"(hi));
    return r;
}
__device__ __forceinline__ void unpack2(unsigned long long v, float& lo, float& hi) {
    asm("mov.b64 {%0, %1}, %2;" : "=f"(lo), "=f"(hi) : "l"(v));
}
__device__ __forceinline__ float wrap2pi(float x) {
    return x - floorf(x * INV_TWO_PI) * TWO_PI;
}
__device__ __forceinline__ float frcp(float x) {
    float r;
    asm("rcp.approx.f32 %0, %1;" : "=f"(r) : "f"(x));
    return r;
}

// ---- parallel pre-kernel: S[t] for all t ----
__global__ void precomp_s(const float* __restrict__ Xr, const float* __restrict__ Xi) {
    int t = blockIdx.x * 256 + threadIdx.x;
    if (t >= TT) return;
    float sr = 0.f, si = 0.f;
    if (t + 1 < TT) {
        const float4* cr = (const float4*)(Xr + t * DD);
        const float4* ci = (const float4*)(Xi + t * DD);
        const float4* nr = (const float4*)(Xr + (t + 1) * DD);
        const float4* ni = (const float4*)(Xi + (t + 1) * DD);
#pragma unroll
        for (int j = 0; j < DD / 4; j++) {
            float4 a = cr[j], b = ci[j], c = nr[j], d = ni[j];
            sr += a.x * c.x - b.x * d.x;  si += a.x * d.x + b.x * c.x;
            sr += a.y * c.y - b.y * d.y;  si += a.y * d.y + b.y * c.y;
            sr += a.z * c.z - b.z * d.z;  si += a.z * d.z + b.z * c.z;
            sr += a.w * c.w - b.w * d.w;  si += a.w * d.w + b.w * c.w;
        }
    }
    Sbuf[t] = make_float2(sr, si);
}

__global__ __launch_bounds__(TPB, 1)
void rds_kernel(const float* __restrict__ Xr, const float* __restrict__ Xi,
                const float* __restrict__ tw, const float* __restrict__ Wr,
                const float* __restrict__ Wi, const float* __restrict__ phi0,
                const float* __restrict__ beta0, float* __restrict__ out) {
    const int tid  = threadIdx.x;
    const int lane = tid & 31;
    const int wid  = tid >> 5;              // 0..7

    // 4-way buffered per-step shared state
    __shared__ __align__(16) float4 xsA[4][DD];     // (xr,xr,xi,xi) per d
    __shared__ __align__(16) float  xsB[4][2 * DD]; // interleaved (xr,xi)
    __shared__ float  s_tgt[4];
    __shared__ __align__(16) float red[2][8];       // per-warp partials

    // factored W: W = alpha * A ; A packed (ar,ai) per d, per neuron
    // NOTE: every loop indexing A MUST be fully unrolled (partial unroll
    // demotes A to local memory — R13 regression).
    unsigned long long A[2][DD];            // 128 regs
    float alpha[2] = {1.0f, 1.0f};
    float phi[2], beta[2], lt[2], dtl[2], sn[2], cs[2];   // gamma = dtl*1e3
    float zr[2], zi[2];
    float err = 0.0f;                       // identical in every thread

#pragma unroll
    for (int n = 0; n < 2; n++) {
        const int g = tid + n * TPB;
#pragma unroll
        for (int d = 0; d < DD; d++)
            A[n][d] = pack2(Wr[g * DD + d], Wi[g * DD + d]);
        phi[n]  = phi0[g];
        beta[n] = beta0[g];
        lt[n]   = 0.0f;
    }

    float* outs   = out;
    float* betas  = out + TT;
    float* gammas = out + TT + (size_t)TT * NN;

    // prologue: x_0 -> buf0, x_1 -> buf1
    if (tid < DD) {
        float xr = Xr[tid], xi = Xi[tid];
        xsA[0][tid] = make_float4(xr, xr, xi, xi);
        xsB[0][2 * tid] = xr; xsB[0][2 * tid + 1] = xi;
        xr = Xr[DD + tid]; xi = Xi[DD + tid];
        xsA[1][tid] = make_float4(xr, xr, xi, xi);
        xsB[1][2 * tid] = xr; xsB[1][2 * tid + 1] = xi;
        if (tid == 0) { s_tgt[0] = tw[0]; s_tgt[1] = tw[1]; }
    }

    // pipelined head for step 0
#pragma unroll
    for (int n = 0; n < 2; n++) {
        dtl[n] = __expf(-0.5f * beta[n]) * 1e-3f;
        lt[n] += dtl[n];
        __sincosf(wrap2pi(10.0f * lt[n] + phi[n]), &sn[n], &cs[n]);
    }

    __syncthreads();

    // Z_0 = A @ x_0 (alpha = 1), both neurons fused over shared x loads
    {
        unsigned long long aA0 = 0ull, aB0 = 0ull, aA1 = 0ull, aB1 = 0ull;
        const ulonglong2* xa = (const ulonglong2*)xsA[0];
#pragma unroll
        for (int d = 0; d < DD; d++) {
            ulonglong2 v = xa[d];
            aA0 = ffma2(A[0][d], v.x, aA0);
            aB0 = ffma2(A[0][d], v.y, aB0);
            aA1 = ffma2(A[1][d], v.x, aA1);
            aB1 = ffma2(A[1][d], v.y, aB1);
        }
        float a0l, a0h, b0l, b0h, a1l, a1h, b1l, b1h;
        unpack2(aA0, a0l, a0h); unpack2(aB0, b0l, b0h);
        unpack2(aA1, a1l, a1h); unpack2(aB1, b1l, b1h);
        zr[0] = a0l - b0h;  zi[0] = b0l + a0h;
        zr[1] = a1l - b1h;  zi[1] = b1l + a1h;
    }

#pragma unroll 1
    for (int t = 0; t < TT; t++) {
        const int b  = t & 3;
        const int bn = (t + 1) & 3;
        const int bp = (t + 2) & 3;
        const int rb = t & 1;

        // ================= PRE-BARRIER =================
        float Y[2], v = 0.0f;
#pragma unroll
        for (int n = 0; n < 2; n++) {
            float dot = cs[n] * zr[n] + sn[n] * zi[n];
            Y[n] = fmaxf(dot, 0.0f);
            v += Y[n] * cs[n];
        }
#pragma unroll
        for (int o = 16; o; o >>= 1)
            v += __shfl_xor_sync(0xffffffffu, v, o);
        if (lane == 0) red[rb][wid] = v;

        // prefetch x_{t+2}, tgt_{t+2}
        if (tid < DD && t + 2 < TT) {
            float xr = Xr[(t + 2) * DD + tid];
            float xi = Xi[(t + 2) * DD + tid];
            xsA[bp][tid] = make_float4(xr, xr, xi, xi);
            xsB[bp][2 * tid]     = xr;
            xsB[bp][2 * tid + 1] = xi;
            if (tid == 0) s_tgt[bp] = tw[t + 2];
        }

        // U = A @ x_{t+1}, both neurons fused (shared x loads)
        float ur[2], ui[2];
        {
            unsigned long long aA0 = 0ull, aB0 = 0ull, aA1 = 0ull, aB1 = 0ull;
            const ulonglong2* xa = (const ulonglong2*)xsA[bn];
#pragma unroll
            for (int d = 0; d < DD; d++) {
                ulonglong2 vv = xa[d];
                aA0 = ffma2(A[0][d], vv.x, aA0);
                aB0 = ffma2(A[0][d], vv.y, aB0);
                aA1 = ffma2(A[1][d], vv.x, aA1);
                aB1 = ffma2(A[1][d], vv.y, aB1);
            }
            float a0l, a0h, b0l, b0h, a1l, a1h, b1l, b1h;
            unpack2(aA0, a0l, a0h); unpack2(aB0, b0l, b0h);
            unpack2(aA1, a1l, a1h); unpack2(aB1, b1l, b1h);
            ur[0] = a0l - b0h;  ui[0] = b0l + a0h;
            ur[1] = a1l - b1h;  ui[1] = b1l + a1h;
        }

        float2 S  = __ldg(&Sbuf[t]);
        float tgt = s_tgt[b];

        // chain hoists (depend only on pre-barrier values; R13-verified safe)
        float rcp_at = frcp(fabsf(tgt) + 0.01f);
        float dphi[2], ex1[2];
#pragma unroll
        for (int n = 0; n < 2; n++) {
            dphi[n] = (2.0f / 512.0f) * (-tgt * sn[n]) * dtl[n];
            // 1 - exp(-2e-3*(gamma+1e-6)), gamma = 1000*dtl
            ex1[n]  = 1.0f - __expf(-2.0f * dtl[n] - 2e-9f);
        }

        __syncthreads();   // the single per-step barrier

        // ================= POST-BARRIER =================
        float4 r0 = *(const float4*)&red[rb][0];
        float4 r1 = *(const float4*)&red[rb][4];
        float out_v = ((r0.x + r0.y) + (r0.z + r0.w))
                    + ((r1.x + r1.y) + (r1.z + r1.w));

        // shared scalar feedback (identical in all threads)
        err = 0.99f * err + 0.01f * fabsf(tgt - out_v);
        float btgt = 3.5f * __expf(-5.0f * (err * rcp_at));

        unsigned long long cpk[2];
#pragma unroll
        for (int n = 0; n < 2; n++) {
            float a_s  = (btgt > beta[n]) ? ex1[n] : 0.03278394f; // 1-exp(-1/30)
            float bnew = beta[n] + a_s * (btgt - beta[n]);
            bnew = fminf(fmaxf(bnew, 0.005f), 5.0f);

            float gg  = 0.05f * Y[n] * dtl[n];
            float ddc = bnew * Y[n] * Y[n] * dtl[n];
            float one = 1.0f - ddc;

            // Z_{t+1} = one * (alpha * U) + gg * S
            float au = one * alpha[n];
            zr[n] = au * ur[n] + gg * S.x;
            zi[n] = au * ui[n] + gg * S.y;

            // factored W update: alpha' = alpha*one ; A += (gg/alpha')*x_t
            float an = alpha[n] * one;
            float c  = __fdividef(gg, an);
            alpha[n] = an;
            cpk[n]   = pack2(c, c);

            // outputs (gamma reconstructed from dtl)
            const int g = tid + n * TPB;
            betas[t * NN + g]  = bnew;
            gammas[t * NN + g] = dtl[n] * 1e3f;

            // phase pull + wrap
            float phin = phi[n] + dphi[n];
            phin -= floorf(phin * INV_TWO_PI) * TWO_PI;
            phi[n] = phin;

            // pipelined head of next step
            beta[n] = bnew;
            dtl[n]  = __expf(-0.5f * bnew) * 1e-3f;
            lt[n]  += dtl[n];
            __sincosf(wrap2pi(10.0f * lt[n] + phin), &sn[n], &cs[n]);
        }
        if (tid == 0) outs[t] = out_v;

        // A update, both neurons fused (shared x_t loads) — FULL unroll
        {
            const ulonglong2* xb = (const ulonglong2*)xsB[b];
#pragma unroll
            for (int j = 0; j < DD / 2; j++) {
                ulonglong2 u = xb[j];
                A[0][2 * j]     = ffma2(cpk[0], u.x, A[0][2 * j]);
                A[0][2 * j + 1] = ffma2(cpk[0], u.y, A[0][2 * j + 1]);
                A[1][2 * j]     = ffma2(cpk[1], u.x, A[1][2 * j]);
                A[1][2 * j + 1] = ffma2(cpk[1], u.y, A[1][2 * j + 1]);
            }
        }

        // periodic renormalization: fold alpha into A — FULL unroll
        if ((t & 127) == 127) {
#pragma unroll
            for (int n = 0; n < 2; n++) {
                unsigned long long apk = pack2(alpha[n], alpha[n]);
#pragma unroll
                for (int d = 0; d < DD; d++)
                    A[n][d] = ffma2(apk, A[n][d], 0ull);
                alpha[n] = 1.0f;
            }
        }
    }
}

extern "C" void kernel_launch(void* const* d_in, const int* in_sizes, int n_in,
                              void* d_out, int out_size) {
    const float* Xr    = (const float*)d_in[0];
    const float* Xi    = (const float*)d_in[1];
    const float* tw    = (const float*)d_in[2];
    const float* Wr    = (const float*)d_in[3];
    const float* Wi    = (const float*)d_in[4];
    const float* phi0  = (const float*)d_in[5];
    const float* beta0 = (const float*)d_in[6];
    float* out = (float*)d_out;
    precomp_s<<<TT / 256, 256>>>(Xr, Xi);
    rds_kernel<<<1, TPB>>>(Xr, Xi, tw, Wr, Wi, phi0, beta0, out);
}